// round 1
// baseline (speedup 1.0000x reference)
#include <cuda_runtime.h>
#include <cstdint>

#define B_ 2
#define T_ 2048
#define C_ 1024
#define H_ 16
#define D_ 64
#define M_ (B_*T_)   // 4096 rows

// Scratch (no allocations allowed — device globals)
__device__ float g_Q[B_*H_*T_*D_];
__device__ float g_K[B_*H_*T_*D_];
__device__ float g_V[B_*H_*T_*D_];
__device__ float g_A[M_*C_];

// ---------------------------------------------------------------------------
// Generic 128x128 fp32 GEMM tile:  C[m,n] = sum_k A[m,k] * Bw[n,k]
// 256 threads, 8x8 per-thread micro-tile, BK=16, single-buffered SMEM.
// ---------------------------------------------------------------------------
#define GBK 16
#define SST 132   // padded row stride (floats), 132*4B = 16B-aligned rows

__device__ __forceinline__ void gemm_tile_compute(
    const float* __restrict__ A, const float* __restrict__ Bw,
    int m0, int n0, float acc[8][8], float* As, float* Bs)
{
    const int tid = threadIdx.x;
    const int tx = tid & 15, ty = tid >> 4;
    for (int k0 = 0; k0 < C_; k0 += GBK) {
        __syncthreads();
        #pragma unroll
        for (int rep = 0; rep < 2; rep++) {
            int f   = tid + rep * 256;
            int row = f >> 2;
            int c4  = (f & 3) * 4;
            float4 va = *(const float4*)&A[(size_t)(m0 + row) * C_ + k0 + c4];
            As[(c4+0)*SST + row] = va.x;
            As[(c4+1)*SST + row] = va.y;
            As[(c4+2)*SST + row] = va.z;
            As[(c4+3)*SST + row] = va.w;
            float4 vb = *(const float4*)&Bw[(size_t)(n0 + row) * C_ + k0 + c4];
            Bs[(c4+0)*SST + row] = vb.x;
            Bs[(c4+1)*SST + row] = vb.y;
            Bs[(c4+2)*SST + row] = vb.z;
            Bs[(c4+3)*SST + row] = vb.w;
        }
        __syncthreads();
        #pragma unroll
        for (int k = 0; k < GBK; k++) {
            float a[8], b[8];
            {
                float4 t0 = *(const float4*)&As[k*SST + ty*8];
                float4 t1 = *(const float4*)&As[k*SST + ty*8 + 4];
                a[0]=t0.x; a[1]=t0.y; a[2]=t0.z; a[3]=t0.w;
                a[4]=t1.x; a[5]=t1.y; a[6]=t1.z; a[7]=t1.w;
                float4 u0 = *(const float4*)&Bs[k*SST + tx*8];
                float4 u1 = *(const float4*)&Bs[k*SST + tx*8 + 4];
                b[0]=u0.x; b[1]=u0.y; b[2]=u0.z; b[3]=u0.w;
                b[4]=u1.x; b[5]=u1.y; b[6]=u1.z; b[7]=u1.w;
            }
            #pragma unroll
            for (int i = 0; i < 8; i++)
                #pragma unroll
                for (int j = 0; j < 8; j++)
                    acc[i][j] += a[i] * b[j];
        }
    }
}

// ---------------------------------------------------------------------------
// Kernel 1: QKV projection. gridDim.z selects Q/K/V. Scatters into [B,H,T,D].
// ---------------------------------------------------------------------------
__global__ __launch_bounds__(256) void qkv_gemm_kernel(
    const float* __restrict__ x,
    const float* __restrict__ Wq, const float* __restrict__ Wk,
    const float* __restrict__ Wv)
{
    __shared__ float As[GBK * SST];
    __shared__ float Bs[GBK * SST];
    const float* Bw = (blockIdx.z == 0) ? Wq : (blockIdx.z == 1) ? Wk : Wv;
    float* dst      = (blockIdx.z == 0) ? g_Q : (blockIdx.z == 1) ? g_K : g_V;

    const int m0 = blockIdx.y * 128, n0 = blockIdx.x * 128;
    float acc[8][8];
    #pragma unroll
    for (int i = 0; i < 8; i++)
        #pragma unroll
        for (int j = 0; j < 8; j++) acc[i][j] = 0.f;

    gemm_tile_compute(x, Bw, m0, n0, acc, As, Bs);

    const int tx = threadIdx.x & 15, ty = threadIdx.x >> 4;
    const int nn = n0 + tx * 8;
    const int h = nn >> 6, d = nn & 63;   // 8 consecutive d within one head
    #pragma unroll
    for (int i = 0; i < 8; i++) {
        int m = m0 + ty * 8 + i;
        int b = m >> 11, t = m & 2047;
        size_t idx = ((size_t)((b * H_ + h) * T_ + t)) * D_ + d;
        *(float4*)&dst[idx]     = make_float4(acc[i][0], acc[i][1], acc[i][2], acc[i][3]);
        *(float4*)&dst[idx + 4] = make_float4(acc[i][4], acc[i][5], acc[i][6], acc[i][7]);
    }
}

// ---------------------------------------------------------------------------
// Kernel 2: causal flash attention. Block = 64 q-rows for one (b,h).
// 256 threads as 16x16 grid, each thread 4 rows x 4 cols.
// ---------------------------------------------------------------------------
#define KST 68   // padded stride for transposed K (68*4B is 16B aligned)

__global__ __launch_bounds__(256) void flash_kernel()
{
    extern __shared__ float sm[];
    float* Qs  = sm;               // 64*64
    float* KsT = Qs + 64 * 64;     // 64*KST (transposed: [d][kv])
    float* Vs  = KsT + 64 * KST;   // 64*64
    float* Ps  = Vs + 64 * 64;     // 64*64

    const int bh = blockIdx.y;
    const int q0 = ((int)gridDim.x - 1 - (int)blockIdx.x) * 64; // heavy tiles first
    const float* Qg = g_Q + (size_t)bh * T_ * D_;
    const float* Kg = g_K + (size_t)bh * T_ * D_;
    const float* Vg = g_V + (size_t)bh * T_ * D_;

    const int tid = threadIdx.x, tx = tid & 15, ty = tid >> 4;

    // Load Q tile, fold in 1/sqrt(D) = 0.125
    #pragma unroll
    for (int rep = 0; rep < 4; rep++) {
        int f = tid + rep * 256;
        int row = f >> 4, c4 = (f & 15) * 4;
        float4 v = *(const float4*)&Qg[(size_t)(q0 + row) * D_ + c4];
        v.x *= 0.125f; v.y *= 0.125f; v.z *= 0.125f; v.w *= 0.125f;
        *(float4*)&Qs[row * 64 + c4] = v;
    }

    float m_i[4], l_i[4], acc[4][4];
    #pragma unroll
    for (int i = 0; i < 4; i++) {
        m_i[i] = -1e30f; l_i[i] = 0.f;
        #pragma unroll
        for (int j = 0; j < 4; j++) acc[i][j] = 0.f;
    }

    for (int kv0 = 0; kv0 <= q0; kv0 += 64) {
        __syncthreads();  // protect Ps/KsT/Vs from previous iteration
        #pragma unroll
        for (int rep = 0; rep < 4; rep++) {
            int f = tid + rep * 256;
            int row = f >> 4, c4 = (f & 15) * 4;
            float4 k4 = *(const float4*)&Kg[(size_t)(kv0 + row) * D_ + c4];
            KsT[(c4+0)*KST + row] = k4.x;
            KsT[(c4+1)*KST + row] = k4.y;
            KsT[(c4+2)*KST + row] = k4.z;
            KsT[(c4+3)*KST + row] = k4.w;
            *(float4*)&Vs[row * 64 + c4] =
                *(const float4*)&Vg[(size_t)(kv0 + row) * D_ + c4];
        }
        __syncthreads();

        // S = Q @ K^T   (scale already folded into Q)
        float s[4][4];
        #pragma unroll
        for (int i = 0; i < 4; i++)
            #pragma unroll
            for (int j = 0; j < 4; j++) s[i][j] = 0.f;

        #pragma unroll
        for (int d4 = 0; d4 < 64; d4 += 4) {
            float qreg[4][4];
            #pragma unroll
            for (int i = 0; i < 4; i++) {
                float4 t = *(const float4*)&Qs[(ty*4 + i) * 64 + d4];
                qreg[i][0]=t.x; qreg[i][1]=t.y; qreg[i][2]=t.z; qreg[i][3]=t.w;
            }
            #pragma unroll
            for (int dd = 0; dd < 4; dd++) {
                float4 kv = *(const float4*)&KsT[(d4 + dd) * KST + tx * 4];
                #pragma unroll
                for (int i = 0; i < 4; i++) {
                    s[i][0] += qreg[i][dd] * kv.x;
                    s[i][1] += qreg[i][dd] * kv.y;
                    s[i][2] += qreg[i][dd] * kv.z;
                    s[i][3] += qreg[i][dd] * kv.w;
                }
            }
        }

        if (kv0 == q0) {   // diagonal tile: causal mask (local col > local row)
            #pragma unroll
            for (int i = 0; i < 4; i++)
                #pragma unroll
                for (int j = 0; j < 4; j++)
                    if (tx * 4 + j > ty * 4 + i) s[i][j] = -1e30f;
        }

        // Online softmax update per row
        #pragma unroll
        for (int i = 0; i < 4; i++) {
            float mloc = fmaxf(fmaxf(s[i][0], s[i][1]), fmaxf(s[i][2], s[i][3]));
            #pragma unroll
            for (int off = 8; off > 0; off >>= 1)
                mloc = fmaxf(mloc, __shfl_xor_sync(0xffffffffu, mloc, off));
            float mnew = fmaxf(m_i[i], mloc);
            float corr = __expf(m_i[i] - mnew);
            m_i[i] = mnew;
            float rs = 0.f;
            #pragma unroll
            for (int j = 0; j < 4; j++) {
                float p = __expf(s[i][j] - mnew);
                s[i][j] = p; rs += p;
            }
            #pragma unroll
            for (int off = 8; off > 0; off >>= 1)
                rs += __shfl_xor_sync(0xffffffffu, rs, off);
            l_i[i] = l_i[i] * corr + rs;
            #pragma unroll
            for (int j = 0; j < 4; j++) acc[i][j] *= corr;
            *(float4*)&Ps[(ty*4 + i) * 64 + tx * 4] =
                make_float4(s[i][0], s[i][1], s[i][2], s[i][3]);
        }
        __syncthreads();

        // O += P @ V
        #pragma unroll
        for (int kv4 = 0; kv4 < 64; kv4 += 4) {
            float preg[4][4];
            #pragma unroll
            for (int i = 0; i < 4; i++) {
                float4 t = *(const float4*)&Ps[(ty*4 + i) * 64 + kv4];
                preg[i][0]=t.x; preg[i][1]=t.y; preg[i][2]=t.z; preg[i][3]=t.w;
            }
            #pragma unroll
            for (int kk = 0; kk < 4; kk++) {
                float4 v = *(const float4*)&Vs[(kv4 + kk) * 64 + tx * 4];
                #pragma unroll
                for (int i = 0; i < 4; i++) {
                    acc[i][0] += preg[i][kk] * v.x;
                    acc[i][1] += preg[i][kk] * v.y;
                    acc[i][2] += preg[i][kk] * v.z;
                    acc[i][3] += preg[i][kk] * v.w;
                }
            }
        }
    }

    // Normalize and write to [B,T,C] layout for the output projection
    const int b = bh >> 4, h = bh & 15;
    #pragma unroll
    for (int i = 0; i < 4; i++) {
        int q = q0 + ty * 4 + i;
        float inv = 1.0f / l_i[i];
        float4 o = make_float4(acc[i][0]*inv, acc[i][1]*inv, acc[i][2]*inv, acc[i][3]*inv);
        *(float4*)&g_A[((size_t)(b * T_ + q)) * C_ + h * D_ + tx * 4] = o;
    }
}

// ---------------------------------------------------------------------------
// Kernel 3: output projection + bias
// ---------------------------------------------------------------------------
__global__ __launch_bounds__(256) void outproj_kernel(
    const float* __restrict__ Wo, const float* __restrict__ bo,
    float* __restrict__ out)
{
    __shared__ float As[GBK * SST];
    __shared__ float Bs[GBK * SST];
    const int m0 = blockIdx.y * 128, n0 = blockIdx.x * 128;
    float acc[8][8];
    #pragma unroll
    for (int i = 0; i < 8; i++)
        #pragma unroll
        for (int j = 0; j < 8; j++) acc[i][j] = 0.f;

    gemm_tile_compute(g_A, Wo, m0, n0, acc, As, Bs);

    const int tx = threadIdx.x & 15, ty = threadIdx.x >> 4;
    const int nn = n0 + tx * 8;
    float4 bia0 = *(const float4*)&bo[nn];
    float4 bia1 = *(const float4*)&bo[nn + 4];
    #pragma unroll
    for (int i = 0; i < 8; i++) {
        int m = m0 + ty * 8 + i;
        *(float4*)&out[(size_t)m * C_ + nn] =
            make_float4(acc[i][0]+bia0.x, acc[i][1]+bia0.y, acc[i][2]+bia0.z, acc[i][3]+bia0.w);
        *(float4*)&out[(size_t)m * C_ + nn + 4] =
            make_float4(acc[i][4]+bia1.x, acc[i][5]+bia1.y, acc[i][6]+bia1.z, acc[i][7]+bia1.w);
    }
}

// ---------------------------------------------------------------------------
extern "C" void kernel_launch(void* const* d_in, const int* in_sizes, int n_in,
                              void* d_out, int out_size)
{
    const float* x  = (const float*)d_in[0];
    const float* Wq = (const float*)d_in[1];
    const float* Wk = (const float*)d_in[2];
    const float* Wv = (const float*)d_in[3];
    const float* Wo = (const float*)d_in[4];
    const float* bo = (const float*)d_in[5];
    float* out = (float*)d_out;

    const int FLASH_SMEM = (64*64 + 64*KST + 64*64 + 64*64) * 4;  // 66560 B
    cudaFuncSetAttribute(flash_kernel,
                         cudaFuncAttributeMaxDynamicSharedMemorySize, FLASH_SMEM);

    dim3 gq(C_ / 128, M_ / 128, 3);     // (8, 32, 3)
    qkv_gemm_kernel<<<gq, 256>>>(x, Wq, Wk, Wv);

    flash_kernel<<<dim3(T_ / 64, B_ * H_), 256, FLASH_SMEM>>>();

    dim3 go(C_ / 128, M_ / 128, 1);     // (8, 32)
    outproj_kernel<<<go, 256>>>(Wo, bo, out);
}

// round 12
// speedup vs baseline: 1.0054x; 1.0054x over previous
#include <cuda_runtime.h>
#include <cstdint>

#define B_ 2
#define T_ 2048
#define C_ 1024
#define H_ 16
#define D_ 64
#define M_ (B_*T_)   // 4096 rows

// Scratch (no allocations allowed — device globals)
__device__ float g_Q[B_*H_*T_*D_];
__device__ float g_K[B_*H_*T_*D_];
__device__ float g_V[B_*H_*T_*D_];
__device__ float g_A[M_*C_];

// ---------------------------------------------------------------------------
// Generic 128x128 fp32 GEMM tile:  C[m,n] = sum_k A[m,k] * Bw[n,k]
// 256 threads, 8x8 per-thread micro-tile, BK=16, single-buffered SMEM.
// ---------------------------------------------------------------------------
#define GBK 16
#define SST 132   // padded row stride (floats), 132*4B = 16B-aligned rows

__device__ __forceinline__ void gemm_tile_compute(
    const float* __restrict__ A, const float* __restrict__ Bw,
    int m0, int n0, float acc[8][8], float* As, float* Bs)
{
    const int tid = threadIdx.x;
    const int tx = tid & 15, ty = tid >> 4;
    for (int k0 = 0; k0 < C_; k0 += GBK) {
        __syncthreads();
        #pragma unroll
        for (int rep = 0; rep < 2; rep++) {
            int f   = tid + rep * 256;
            int row = f >> 2;
            int c4  = (f & 3) * 4;
            float4 va = *(const float4*)&A[(size_t)(m0 + row) * C_ + k0 + c4];
            As[(c4+0)*SST + row] = va.x;
            As[(c4+1)*SST + row] = va.y;
            As[(c4+2)*SST + row] = va.z;
            As[(c4+3)*SST + row] = va.w;
            float4 vb = *(const float4*)&Bw[(size_t)(n0 + row) * C_ + k0 + c4];
            Bs[(c4+0)*SST + row] = vb.x;
            Bs[(c4+1)*SST + row] = vb.y;
            Bs[(c4+2)*SST + row] = vb.z;
            Bs[(c4+3)*SST + row] = vb.w;
        }
        __syncthreads();
        #pragma unroll
        for (int k = 0; k < GBK; k++) {
            float a[8], b[8];
            {
                float4 t0 = *(const float4*)&As[k*SST + ty*8];
                float4 t1 = *(const float4*)&As[k*SST + ty*8 + 4];
                a[0]=t0.x; a[1]=t0.y; a[2]=t0.z; a[3]=t0.w;
                a[4]=t1.x; a[5]=t1.y; a[6]=t1.z; a[7]=t1.w;
                float4 u0 = *(const float4*)&Bs[k*SST + tx*8];
                float4 u1 = *(const float4*)&Bs[k*SST + tx*8 + 4];
                b[0]=u0.x; b[1]=u0.y; b[2]=u0.z; b[3]=u0.w;
                b[4]=u1.x; b[5]=u1.y; b[6]=u1.z; b[7]=u1.w;
            }
            #pragma unroll
            for (int i = 0; i < 8; i++)
                #pragma unroll
                for (int j = 0; j < 8; j++)
                    acc[i][j] += a[i] * b[j];
        }
    }
}

// ---------------------------------------------------------------------------
// Kernel 1: QKV projection. gridDim.z selects Q/K/V. Scatters into [B,H,T,D].
// ---------------------------------------------------------------------------
__global__ __launch_bounds__(256) void qkv_gemm_kernel(
    const float* __restrict__ x,
    const float* __restrict__ Wq, const float* __restrict__ Wk,
    const float* __restrict__ Wv)
{
    __shared__ float As[GBK * SST];
    __shared__ float Bs[GBK * SST];
    const float* Bw = (blockIdx.z == 0) ? Wq : (blockIdx.z == 1) ? Wk : Wv;
    float* dst      = (blockIdx.z == 0) ? g_Q : (blockIdx.z == 1) ? g_K : g_V;

    const int m0 = blockIdx.y * 128, n0 = blockIdx.x * 128;
    float acc[8][8];
    #pragma unroll
    for (int i = 0; i < 8; i++)
        #pragma unroll
        for (int j = 0; j < 8; j++) acc[i][j] = 0.f;

    gemm_tile_compute(x, Bw, m0, n0, acc, As, Bs);

    const int tx = threadIdx.x & 15, ty = threadIdx.x >> 4;
    const int nn = n0 + tx * 8;
    const int h = nn >> 6, d = nn & 63;   // 8 consecutive d within one head
    #pragma unroll
    for (int i = 0; i < 8; i++) {
        int m = m0 + ty * 8 + i;
        int b = m >> 11, t = m & 2047;
        size_t idx = ((size_t)((b * H_ + h) * T_ + t)) * D_ + d;
        *(float4*)&dst[idx]     = make_float4(acc[i][0], acc[i][1], acc[i][2], acc[i][3]);
        *(float4*)&dst[idx + 4] = make_float4(acc[i][4], acc[i][5], acc[i][6], acc[i][7]);
    }
}

// ---------------------------------------------------------------------------
// Kernel 2: causal flash attention. Block = 64 q-rows for one (b,h).
// 256 threads as 16x16 grid, each thread 4 rows x 4 cols.
// ---------------------------------------------------------------------------
#define KST 68   // padded stride for transposed K (68*4B is 16B aligned)

__global__ __launch_bounds__(256) void flash_kernel()
{
    extern __shared__ float sm[];
    float* Qs  = sm;               // 64*64
    float* KsT = Qs + 64 * 64;     // 64*KST (transposed: [d][kv])
    float* Vs  = KsT + 64 * KST;   // 64*64
    float* Ps  = Vs + 64 * 64;     // 64*64

    const int bh = blockIdx.y;
    const int q0 = ((int)gridDim.x - 1 - (int)blockIdx.x) * 64; // heavy tiles first
    const float* Qg = g_Q + (size_t)bh * T_ * D_;
    const float* Kg = g_K + (size_t)bh * T_ * D_;
    const float* Vg = g_V + (size_t)bh * T_ * D_;

    const int tid = threadIdx.x, tx = tid & 15, ty = tid >> 4;

    // Load Q tile, fold in 1/sqrt(D) = 0.125
    #pragma unroll
    for (int rep = 0; rep < 4; rep++) {
        int f = tid + rep * 256;
        int row = f >> 4, c4 = (f & 15) * 4;
        float4 v = *(const float4*)&Qg[(size_t)(q0 + row) * D_ + c4];
        v.x *= 0.125f; v.y *= 0.125f; v.z *= 0.125f; v.w *= 0.125f;
        *(float4*)&Qs[row * 64 + c4] = v;
    }

    float m_i[4], l_i[4], acc[4][4];
    #pragma unroll
    for (int i = 0; i < 4; i++) {
        m_i[i] = -1e30f; l_i[i] = 0.f;
        #pragma unroll
        for (int j = 0; j < 4; j++) acc[i][j] = 0.f;
    }

    for (int kv0 = 0; kv0 <= q0; kv0 += 64) {
        __syncthreads();  // protect Ps/KsT/Vs from previous iteration
        #pragma unroll
        for (int rep = 0; rep < 4; rep++) {
            int f = tid + rep * 256;
            int row = f >> 4, c4 = (f & 15) * 4;
            float4 k4 = *(const float4*)&Kg[(size_t)(kv0 + row) * D_ + c4];
            KsT[(c4+0)*KST + row] = k4.x;
            KsT[(c4+1)*KST + row] = k4.y;
            KsT[(c4+2)*KST + row] = k4.z;
            KsT[(c4+3)*KST + row] = k4.w;
            *(float4*)&Vs[row * 64 + c4] =
                *(const float4*)&Vg[(size_t)(kv0 + row) * D_ + c4];
        }
        __syncthreads();

        // S = Q @ K^T   (scale already folded into Q)
        float s[4][4];
        #pragma unroll
        for (int i = 0; i < 4; i++)
            #pragma unroll
            for (int j = 0; j < 4; j++) s[i][j] = 0.f;

        #pragma unroll
        for (int d4 = 0; d4 < 64; d4 += 4) {
            float qreg[4][4];
            #pragma unroll
            for (int i = 0; i < 4; i++) {
                float4 t = *(const float4*)&Qs[(ty*4 + i) * 64 + d4];
                qreg[i][0]=t.x; qreg[i][1]=t.y; qreg[i][2]=t.z; qreg[i][3]=t.w;
            }
            #pragma unroll
            for (int dd = 0; dd < 4; dd++) {
                float4 kv = *(const float4*)&KsT[(d4 + dd) * KST + tx * 4];
                #pragma unroll
                for (int i = 0; i < 4; i++) {
                    s[i][0] += qreg[i][dd] * kv.x;
                    s[i][1] += qreg[i][dd] * kv.y;
                    s[i][2] += qreg[i][dd] * kv.z;
                    s[i][3] += qreg[i][dd] * kv.w;
                }
            }
        }

        if (kv0 == q0) {   // diagonal tile: causal mask (local col > local row)
            #pragma unroll
            for (int i = 0; i < 4; i++)
                #pragma unroll
                for (int j = 0; j < 4; j++)
                    if (tx * 4 + j > ty * 4 + i) s[i][j] = -1e30f;
        }

        // Online softmax update per row
        #pragma unroll
        for (int i = 0; i < 4; i++) {
            float mloc = fmaxf(fmaxf(s[i][0], s[i][1]), fmaxf(s[i][2], s[i][3]));
            #pragma unroll
            for (int off = 8; off > 0; off >>= 1)
                mloc = fmaxf(mloc, __shfl_xor_sync(0xffffffffu, mloc, off));
            float mnew = fmaxf(m_i[i], mloc);
            float corr = __expf(m_i[i] - mnew);
            m_i[i] = mnew;
            float rs = 0.f;
            #pragma unroll
            for (int j = 0; j < 4; j++) {
                float p = __expf(s[i][j] - mnew);
                s[i][j] = p; rs += p;
            }
            #pragma unroll
            for (int off = 8; off > 0; off >>= 1)
                rs += __shfl_xor_sync(0xffffffffu, rs, off);
            l_i[i] = l_i[i] * corr + rs;
            #pragma unroll
            for (int j = 0; j < 4; j++) acc[i][j] *= corr;
            *(float4*)&Ps[(ty*4 + i) * 64 + tx * 4] =
                make_float4(s[i][0], s[i][1], s[i][2], s[i][3]);
        }
        __syncthreads();

        // O += P @ V
        #pragma unroll
        for (int kv4 = 0; kv4 < 64; kv4 += 4) {
            float preg[4][4];
            #pragma unroll
            for (int i = 0; i < 4; i++) {
                float4 t = *(const float4*)&Ps[(ty*4 + i) * 64 + kv4];
                preg[i][0]=t.x; preg[i][1]=t.y; preg[i][2]=t.z; preg[i][3]=t.w;
            }
            #pragma unroll
            for (int kk = 0; kk < 4; kk++) {
                float4 v = *(const float4*)&Vs[(kv4 + kk) * 64 + tx * 4];
                #pragma unroll
                for (int i = 0; i < 4; i++) {
                    acc[i][0] += preg[i][kk] * v.x;
                    acc[i][1] += preg[i][kk] * v.y;
                    acc[i][2] += preg[i][kk] * v.z;
                    acc[i][3] += preg[i][kk] * v.w;
                }
            }
        }
    }

    // Normalize and write to [B,T,C] layout for the output projection
    const int b = bh >> 4, h = bh & 15;
    #pragma unroll
    for (int i = 0; i < 4; i++) {
        int q = q0 + ty * 4 + i;
        float inv = 1.0f / l_i[i];
        float4 o = make_float4(acc[i][0]*inv, acc[i][1]*inv, acc[i][2]*inv, acc[i][3]*inv);
        *(float4*)&g_A[((size_t)(b * T_ + q)) * C_ + h * D_ + tx * 4] = o;
    }
}

// ---------------------------------------------------------------------------
// Kernel 3: output projection + bias
// ---------------------------------------------------------------------------
__global__ __launch_bounds__(256) void outproj_kernel(
    const float* __restrict__ Wo, const float* __restrict__ bo,
    float* __restrict__ out)
{
    __shared__ float As[GBK * SST];
    __shared__ float Bs[GBK * SST];
    const int m0 = blockIdx.y * 128, n0 = blockIdx.x * 128;
    float acc[8][8];
    #pragma unroll
    for (int i = 0; i < 8; i++)
        #pragma unroll
        for (int j = 0; j < 8; j++) acc[i][j] = 0.f;

    gemm_tile_compute(g_A, Wo, m0, n0, acc, As, Bs);

    const int tx = threadIdx.x & 15, ty = threadIdx.x >> 4;
    const int nn = n0 + tx * 8;
    float4 bia0 = *(const float4*)&bo[nn];
    float4 bia1 = *(const float4*)&bo[nn + 4];
    #pragma unroll
    for (int i = 0; i < 8; i++) {
        int m = m0 + ty * 8 + i;
        *(float4*)&out[(size_t)m * C_ + nn] =
            make_float4(acc[i][0]+bia0.x, acc[i][1]+bia0.y, acc[i][2]+bia0.z, acc[i][3]+bia0.w);
        *(float4*)&out[(size_t)m * C_ + nn + 4] =
            make_float4(acc[i][4]+bia1.x, acc[i][5]+bia1.y, acc[i][6]+bia1.z, acc[i][7]+bia1.w);
    }
}

// ---------------------------------------------------------------------------
extern "C" void kernel_launch(void* const* d_in, const int* in_sizes, int n_in,
                              void* d_out, int out_size)
{
    const float* x  = (const float*)d_in[0];
    const float* Wq = (const float*)d_in[1];
    const float* Wk = (const float*)d_in[2];
    const float* Wv = (const float*)d_in[3];
    const float* Wo = (const float*)d_in[4];
    const float* bo = (const float*)d_in[5];
    float* out = (float*)d_out;

    const int FLASH_SMEM = (64*64 + 64*KST + 64*64 + 64*64) * 4;  // 66560 B
    cudaFuncSetAttribute(flash_kernel,
                         cudaFuncAttributeMaxDynamicSharedMemorySize, FLASH_SMEM);

    dim3 gq(C_ / 128, M_ / 128, 3);     // (8, 32, 3)
    qkv_gemm_kernel<<<gq, 256>>>(x, Wq, Wk, Wv);

    flash_kernel<<<dim3(T_ / 64, B_ * H_), 256, FLASH_SMEM>>>();

    dim3 go(C_ / 128, M_ / 128, 1);     // (8, 32)
    outproj_kernel<<<go, 256>>>(Wo, bo, out);
}

// round 13
// speedup vs baseline: 1.0185x; 1.0131x over previous
#include <cuda_runtime.h>
#include <cstdint>

#define B_ 2
#define T_ 2048
#define C_ 1024
#define H_ 16
#define D_ 64
#define M_ (B_*T_)   // 4096 rows

// Scratch (no allocations allowed — device globals)
__device__ float g_Q[B_*H_*T_*D_];
__device__ float g_K[B_*H_*T_*D_];
__device__ float g_V[B_*H_*T_*D_];
__device__ float g_A[M_*C_];

// ---------------------------------------------------------------------------
// Generic 128x128 fp32 GEMM tile:  C[m,n] = sum_k A[m,k] * Bw[n,k]
// 256 threads, 8x8 per-thread micro-tile, BK=16.
// v2: DOUBLE-buffered SMEM + unconditional register prefetch (clamped index),
// one __syncthreads per k-block. All locals unconditionally initialized;
// no inline asm (both are lmem/guard triggers on this toolchain).
// ---------------------------------------------------------------------------
#define GBK 16
#define SST 132   // padded row stride (floats), 132*4B = 16B-aligned rows
#define NKB (C_/GBK)   // 64

__device__ __forceinline__ void gemm_tile_compute(
    const float* __restrict__ A, const float* __restrict__ Bw,
    int m0, int n0, float acc[8][8],
    float (*As)[GBK * SST], float (*Bs)[GBK * SST])
{
    const int tid = threadIdx.x;
    const int tx = tid & 15, ty = tid >> 4;
    // Loader geometry (same mapping as rep-loop in R1): rows row0,row0+64, cols c4..c4+3
    const int row0 = tid >> 2;          // 0..63
    const int c4   = (tid & 3) * 4;     // 0,4,8,12
    const float* Ap0 = &A[(size_t)(m0 + row0)      * C_ + c4];
    const float* Ap1 = &A[(size_t)(m0 + row0 + 64) * C_ + c4];
    const float* Bp0 = &Bw[(size_t)(n0 + row0)      * C_ + c4];
    const float* Bp1 = &Bw[(size_t)(n0 + row0 + 64) * C_ + c4];

    // Prologue: stage 0 (unconditional loads)
    float4 va0 = *(const float4*)(Ap0);
    float4 va1 = *(const float4*)(Ap1);
    float4 vb0 = *(const float4*)(Bp0);
    float4 vb1 = *(const float4*)(Bp1);
    As[0][(c4+0)*SST + row0] = va0.x; As[0][(c4+1)*SST + row0] = va0.y;
    As[0][(c4+2)*SST + row0] = va0.z; As[0][(c4+3)*SST + row0] = va0.w;
    As[0][(c4+0)*SST + row0+64] = va1.x; As[0][(c4+1)*SST + row0+64] = va1.y;
    As[0][(c4+2)*SST + row0+64] = va1.z; As[0][(c4+3)*SST + row0+64] = va1.w;
    Bs[0][(c4+0)*SST + row0] = vb0.x; Bs[0][(c4+1)*SST + row0] = vb0.y;
    Bs[0][(c4+2)*SST + row0] = vb0.z; Bs[0][(c4+3)*SST + row0] = vb0.w;
    Bs[0][(c4+0)*SST + row0+64] = vb1.x; Bs[0][(c4+1)*SST + row0+64] = vb1.y;
    Bs[0][(c4+2)*SST + row0+64] = vb1.z; Bs[0][(c4+3)*SST + row0+64] = vb1.w;
    __syncthreads();

    for (int kb = 0; kb < NKB; kb++) {
        const int buf = kb & 1;
        const int nb  = buf ^ 1;
        // Unconditional prefetch of next k-block; last iteration re-reads the
        // current block (in-bounds, result never consumed). No divergently-
        // uninitialized locals.
        const int kn = (kb + 1 < NKB) ? (kb + 1) * GBK : kb * GBK;
        va0 = *(const float4*)(Ap0 + kn);
        va1 = *(const float4*)(Ap1 + kn);
        vb0 = *(const float4*)(Bp0 + kn);
        vb1 = *(const float4*)(Bp1 + kn);

        #pragma unroll
        for (int k = 0; k < GBK; k++) {
            float a[8], b[8];
            {
                float4 t0 = *(const float4*)&As[buf][k*SST + ty*8];
                float4 t1 = *(const float4*)&As[buf][k*SST + ty*8 + 4];
                a[0]=t0.x; a[1]=t0.y; a[2]=t0.z; a[3]=t0.w;
                a[4]=t1.x; a[5]=t1.y; a[6]=t1.z; a[7]=t1.w;
                float4 u0 = *(const float4*)&Bs[buf][k*SST + tx*8];
                float4 u1 = *(const float4*)&Bs[buf][k*SST + tx*8 + 4];
                b[0]=u0.x; b[1]=u0.y; b[2]=u0.z; b[3]=u0.w;
                b[4]=u1.x; b[5]=u1.y; b[6]=u1.z; b[7]=u1.w;
            }
            #pragma unroll
            for (int i = 0; i < 8; i++)
                #pragma unroll
                for (int j = 0; j < 8; j++)
                    acc[i][j] += a[i] * b[j];
        }

        // Write prefetched block into the other buffer (safe: consumers of nb
        // finished it before the sync that ended iteration kb-1).
        As[nb][(c4+0)*SST + row0] = va0.x; As[nb][(c4+1)*SST + row0] = va0.y;
        As[nb][(c4+2)*SST + row0] = va0.z; As[nb][(c4+3)*SST + row0] = va0.w;
        As[nb][(c4+0)*SST + row0+64] = va1.x; As[nb][(c4+1)*SST + row0+64] = va1.y;
        As[nb][(c4+2)*SST + row0+64] = va1.z; As[nb][(c4+3)*SST + row0+64] = va1.w;
        Bs[nb][(c4+0)*SST + row0] = vb0.x; Bs[nb][(c4+1)*SST + row0] = vb0.y;
        Bs[nb][(c4+2)*SST + row0] = vb0.z; Bs[nb][(c4+3)*SST + row0] = vb0.w;
        Bs[nb][(c4+0)*SST + row0+64] = vb1.x; Bs[nb][(c4+1)*SST + row0+64] = vb1.y;
        Bs[nb][(c4+2)*SST + row0+64] = vb1.z; Bs[nb][(c4+3)*SST + row0+64] = vb1.w;
        __syncthreads();
    }
}

// ---------------------------------------------------------------------------
// Kernel 1: QKV projection. gridDim.z selects Q/K/V. Scatters into [B,H,T,D].
// ---------------------------------------------------------------------------
__global__ __launch_bounds__(256) void qkv_gemm_kernel(
    const float* __restrict__ x,
    const float* __restrict__ Wq, const float* __restrict__ Wk,
    const float* __restrict__ Wv)
{
    __shared__ float As[2][GBK * SST];
    __shared__ float Bs[2][GBK * SST];
    const float* Bw = (blockIdx.z == 0) ? Wq : (blockIdx.z == 1) ? Wk : Wv;
    float* dst      = (blockIdx.z == 0) ? g_Q : (blockIdx.z == 1) ? g_K : g_V;

    const int m0 = blockIdx.y * 128, n0 = blockIdx.x * 128;
    float acc[8][8];
    #pragma unroll
    for (int i = 0; i < 8; i++)
        #pragma unroll
        for (int j = 0; j < 8; j++) acc[i][j] = 0.f;

    gemm_tile_compute(x, Bw, m0, n0, acc, As, Bs);

    const int tx = threadIdx.x & 15, ty = threadIdx.x >> 4;
    const int nn = n0 + tx * 8;
    const int h = nn >> 6, d = nn & 63;   // 8 consecutive d within one head
    #pragma unroll
    for (int i = 0; i < 8; i++) {
        int m = m0 + ty * 8 + i;
        int b = m >> 11, t = m & 2047;
        size_t idx = ((size_t)((b * H_ + h) * T_ + t)) * D_ + d;
        *(float4*)&dst[idx]     = make_float4(acc[i][0], acc[i][1], acc[i][2], acc[i][3]);
        *(float4*)&dst[idx + 4] = make_float4(acc[i][4], acc[i][5], acc[i][6], acc[i][7]);
    }
}

// ---------------------------------------------------------------------------
// Kernel 2: causal flash attention (byte-identical to R1/R12 — known clean)
// ---------------------------------------------------------------------------
#define KST 68   // padded stride for transposed K (68*4B is 16B aligned)

__global__ __launch_bounds__(256) void flash_kernel()
{
    extern __shared__ float sm[];
    float* Qs  = sm;               // 64*64
    float* KsT = Qs + 64 * 64;     // 64*KST (transposed: [d][kv])
    float* Vs  = KsT + 64 * KST;   // 64*64
    float* Ps  = Vs + 64 * 64;     // 64*64

    const int bh = blockIdx.y;
    const int q0 = ((int)gridDim.x - 1 - (int)blockIdx.x) * 64; // heavy tiles first
    const float* Qg = g_Q + (size_t)bh * T_ * D_;
    const float* Kg = g_K + (size_t)bh * T_ * D_;
    const float* Vg = g_V + (size_t)bh * T_ * D_;

    const int tid = threadIdx.x, tx = tid & 15, ty = tid >> 4;

    // Load Q tile, fold in 1/sqrt(D) = 0.125
    #pragma unroll
    for (int rep = 0; rep < 4; rep++) {
        int f = tid + rep * 256;
        int row = f >> 4, c4 = (f & 15) * 4;
        float4 v = *(const float4*)&Qg[(size_t)(q0 + row) * D_ + c4];
        v.x *= 0.125f; v.y *= 0.125f; v.z *= 0.125f; v.w *= 0.125f;
        *(float4*)&Qs[row * 64 + c4] = v;
    }

    float m_i[4], l_i[4], acc[4][4];
    #pragma unroll
    for (int i = 0; i < 4; i++) {
        m_i[i] = -1e30f; l_i[i] = 0.f;
        #pragma unroll
        for (int j = 0; j < 4; j++) acc[i][j] = 0.f;
    }

    for (int kv0 = 0; kv0 <= q0; kv0 += 64) {
        __syncthreads();  // protect Ps/KsT/Vs from previous iteration
        #pragma unroll
        for (int rep = 0; rep < 4; rep++) {
            int f = tid + rep * 256;
            int row = f >> 4, c4 = (f & 15) * 4;
            float4 k4 = *(const float4*)&Kg[(size_t)(kv0 + row) * D_ + c4];
            KsT[(c4+0)*KST + row] = k4.x;
            KsT[(c4+1)*KST + row] = k4.y;
            KsT[(c4+2)*KST + row] = k4.z;
            KsT[(c4+3)*KST + row] = k4.w;
            *(float4*)&Vs[row * 64 + c4] =
                *(const float4*)&Vg[(size_t)(kv0 + row) * D_ + c4];
        }
        __syncthreads();

        // S = Q @ K^T   (scale already folded into Q)
        float s[4][4];
        #pragma unroll
        for (int i = 0; i < 4; i++)
            #pragma unroll
            for (int j = 0; j < 4; j++) s[i][j] = 0.f;

        #pragma unroll
        for (int d4 = 0; d4 < 64; d4 += 4) {
            float qreg[4][4];
            #pragma unroll
            for (int i = 0; i < 4; i++) {
                float4 t = *(const float4*)&Qs[(ty*4 + i) * 64 + d4];
                qreg[i][0]=t.x; qreg[i][1]=t.y; qreg[i][2]=t.z; qreg[i][3]=t.w;
            }
            #pragma unroll
            for (int dd = 0; dd < 4; dd++) {
                float4 kv = *(const float4*)&KsT[(d4 + dd) * KST + tx * 4];
                #pragma unroll
                for (int i = 0; i < 4; i++) {
                    s[i][0] += qreg[i][dd] * kv.x;
                    s[i][1] += qreg[i][dd] * kv.y;
                    s[i][2] += qreg[i][dd] * kv.z;
                    s[i][3] += qreg[i][dd] * kv.w;
                }
            }
        }

        if (kv0 == q0) {   // diagonal tile: causal mask (local col > local row)
            #pragma unroll
            for (int i = 0; i < 4; i++)
                #pragma unroll
                for (int j = 0; j < 4; j++)
                    if (tx * 4 + j > ty * 4 + i) s[i][j] = -1e30f;
        }

        // Online softmax update per row
        #pragma unroll
        for (int i = 0; i < 4; i++) {
            float mloc = fmaxf(fmaxf(s[i][0], s[i][1]), fmaxf(s[i][2], s[i][3]));
            #pragma unroll
            for (int off = 8; off > 0; off >>= 1)
                mloc = fmaxf(mloc, __shfl_xor_sync(0xffffffffu, mloc, off));
            float mnew = fmaxf(m_i[i], mloc);
            float corr = __expf(m_i[i] - mnew);
            m_i[i] = mnew;
            float rs = 0.f;
            #pragma unroll
            for (int j = 0; j < 4; j++) {
                float p = __expf(s[i][j] - mnew);
                s[i][j] = p; rs += p;
            }
            #pragma unroll
            for (int off = 8; off > 0; off >>= 1)
                rs += __shfl_xor_sync(0xffffffffu, rs, off);
            l_i[i] = l_i[i] * corr + rs;
            #pragma unroll
            for (int j = 0; j < 4; j++) acc[i][j] *= corr;
            *(float4*)&Ps[(ty*4 + i) * 64 + tx * 4] =
                make_float4(s[i][0], s[i][1], s[i][2], s[i][3]);
        }
        __syncthreads();

        // O += P @ V
        #pragma unroll
        for (int kv4 = 0; kv4 < 64; kv4 += 4) {
            float preg[4][4];
            #pragma unroll
            for (int i = 0; i < 4; i++) {
                float4 t = *(const float4*)&Ps[(ty*4 + i) * 64 + kv4];
                preg[i][0]=t.x; preg[i][1]=t.y; preg[i][2]=t.z; preg[i][3]=t.w;
            }
            #pragma unroll
            for (int kk = 0; kk < 4; kk++) {
                float4 v = *(const float4*)&Vs[(kv4 + kk) * 64 + tx * 4];
                #pragma unroll
                for (int i = 0; i < 4; i++) {
                    acc[i][0] += preg[i][kk] * v.x;
                    acc[i][1] += preg[i][kk] * v.y;
                    acc[i][2] += preg[i][kk] * v.z;
                    acc[i][3] += preg[i][kk] * v.w;
                }
            }
        }
    }

    // Normalize and write to [B,T,C] layout for the output projection
    const int b = bh >> 4, h = bh & 15;
    #pragma unroll
    for (int i = 0; i < 4; i++) {
        int q = q0 + ty * 4 + i;
        float inv = 1.0f / l_i[i];
        float4 o = make_float4(acc[i][0]*inv, acc[i][1]*inv, acc[i][2]*inv, acc[i][3]*inv);
        *(float4*)&g_A[((size_t)(b * T_ + q)) * C_ + h * D_ + tx * 4] = o;
    }
}

// ---------------------------------------------------------------------------
// Kernel 3: output projection + bias
// ---------------------------------------------------------------------------
__global__ __launch_bounds__(256) void outproj_kernel(
    const float* __restrict__ Wo, const float* __restrict__ bo,
    float* __restrict__ out)
{
    __shared__ float As[2][GBK * SST];
    __shared__ float Bs[2][GBK * SST];
    const int m0 = blockIdx.y * 128, n0 = blockIdx.x * 128;
    float acc[8][8];
    #pragma unroll
    for (int i = 0; i < 8; i++)
        #pragma unroll
        for (int j = 0; j < 8; j++) acc[i][j] = 0.f;

    gemm_tile_compute(g_A, Wo, m0, n0, acc, As, Bs);

    const int tx = threadIdx.x & 15, ty = threadIdx.x >> 4;
    const int nn = n0 + tx * 8;
    float4 bia0 = *(const float4*)&bo[nn];
    float4 bia1 = *(const float4*)&bo[nn + 4];
    #pragma unroll
    for (int i = 0; i < 8; i++) {
        int m = m0 + ty * 8 + i;
        *(float4*)&out[(size_t)m * C_ + nn] =
            make_float4(acc[i][0]+bia0.x, acc[i][1]+bia0.y, acc[i][2]+bia0.z, acc[i][3]+bia0.w);
        *(float4*)&out[(size_t)m * C_ + nn + 4] =
            make_float4(acc[i][4]+bia1.x, acc[i][5]+bia1.y, acc[i][6]+bia1.z, acc[i][7]+bia1.w);
    }
}

// ---------------------------------------------------------------------------
extern "C" void kernel_launch(void* const* d_in, const int* in_sizes, int n_in,
                              void* d_out, int out_size)
{
    const float* x  = (const float*)d_in[0];
    const float* Wq = (const float*)d_in[1];
    const float* Wk = (const float*)d_in[2];
    const float* Wv = (const float*)d_in[3];
    const float* Wo = (const float*)d_in[4];
    const float* bo = (const float*)d_in[5];
    float* out = (float*)d_out;

    const int FLASH_SMEM = (64*64 + 64*KST + 64*64 + 64*64) * 4;  // 66560 B
    cudaFuncSetAttribute(flash_kernel,
                         cudaFuncAttributeMaxDynamicSharedMemorySize, FLASH_SMEM);

    dim3 gq(C_ / 128, M_ / 128, 3);     // (8, 32, 3)
    qkv_gemm_kernel<<<gq, 256>>>(x, Wq, Wk, Wv);

    flash_kernel<<<dim3(T_ / 64, B_ * H_), 256, FLASH_SMEM>>>();

    dim3 go(C_ / 128, M_ / 128, 1);     // (8, 32)
    outproj_kernel<<<go, 256>>>(Wo, bo, out);
}

// round 14
// speedup vs baseline: 1.0525x; 1.0334x over previous
#include <cuda_runtime.h>
#include <cstdint>

#define B_ 2
#define T_ 2048
#define C_ 1024
#define H_ 16
#define D_ 64
#define M_ (B_*T_)   // 4096 rows

// Scratch (no allocations allowed — device globals)
__device__ float g_Q[B_*H_*T_*D_];
__device__ float g_K[B_*H_*T_*D_];
__device__ float g_V[B_*H_*T_*D_];
__device__ float g_A[M_*C_];

// ---------------------------------------------------------------------------
// Generic 128x128 fp32 GEMM tile:  C[m,n] = sum_k A[m,k] * Bw[n,k]
// 256 threads, 8x8 per-thread micro-tile SPLIT as 2x2 quadrants of 4x4 so
// every SMEM fragment load is a consecutive float4 (conflict-free).
// Double-buffered SMEM + unconditional register prefetch, one sync/k-block.
// All locals unconditionally initialized; no inline asm (lmem/guard triggers).
// ---------------------------------------------------------------------------
#define GBK 16
#define SST 132   // padded row stride (floats), 132*4B = 16B-aligned rows
#define NKB (C_/GBK)   // 64

__device__ __forceinline__ void gemm_tile_compute(
    const float* __restrict__ A, const float* __restrict__ Bw,
    int m0, int n0, float acc[8][8],
    float (*As)[GBK * SST], float (*Bs)[GBK * SST])
{
    const int tid = threadIdx.x;
    const int tx = tid & 15, ty = tid >> 4;
    // Loader geometry: rows row0,row0+64, k-cols c4..c4+3
    const int row0 = tid >> 2;          // 0..63
    const int c4   = (tid & 3) * 4;     // 0,4,8,12
    const float* Ap0 = &A[(size_t)(m0 + row0)      * C_ + c4];
    const float* Ap1 = &A[(size_t)(m0 + row0 + 64) * C_ + c4];
    const float* Bp0 = &Bw[(size_t)(n0 + row0)      * C_ + c4];
    const float* Bp1 = &Bw[(size_t)(n0 + row0 + 64) * C_ + c4];

    // Prologue: stage 0 (unconditional loads)
    float4 va0 = *(const float4*)(Ap0);
    float4 va1 = *(const float4*)(Ap1);
    float4 vb0 = *(const float4*)(Bp0);
    float4 vb1 = *(const float4*)(Bp1);
    As[0][(c4+0)*SST + row0] = va0.x; As[0][(c4+1)*SST + row0] = va0.y;
    As[0][(c4+2)*SST + row0] = va0.z; As[0][(c4+3)*SST + row0] = va0.w;
    As[0][(c4+0)*SST + row0+64] = va1.x; As[0][(c4+1)*SST + row0+64] = va1.y;
    As[0][(c4+2)*SST + row0+64] = va1.z; As[0][(c4+3)*SST + row0+64] = va1.w;
    Bs[0][(c4+0)*SST + row0] = vb0.x; Bs[0][(c4+1)*SST + row0] = vb0.y;
    Bs[0][(c4+2)*SST + row0] = vb0.z; Bs[0][(c4+3)*SST + row0] = vb0.w;
    Bs[0][(c4+0)*SST + row0+64] = vb1.x; Bs[0][(c4+1)*SST + row0+64] = vb1.y;
    Bs[0][(c4+2)*SST + row0+64] = vb1.z; Bs[0][(c4+3)*SST + row0+64] = vb1.w;
    __syncthreads();

    for (int kb = 0; kb < NKB; kb++) {
        const int buf = kb & 1;
        const int nb  = buf ^ 1;
        // Unconditional prefetch (last iteration re-reads current block:
        // in-bounds, never consumed). No divergently-uninitialized locals.
        const int kn = (kb + 1 < NKB) ? (kb + 1) * GBK : kb * GBK;
        va0 = *(const float4*)(Ap0 + kn);
        va1 = *(const float4*)(Ap1 + kn);
        vb0 = *(const float4*)(Bp0 + kn);
        vb1 = *(const float4*)(Bp1 + kn);

        #pragma unroll
        for (int k = 0; k < GBK; k++) {
            float a[8], b[8];
            {
                // Quadrant-split fragments: consecutive float4s, conflict-free
                float4 t0 = *(const float4*)&As[buf][k*SST + ty*4];
                float4 t1 = *(const float4*)&As[buf][k*SST + 64 + ty*4];
                a[0]=t0.x; a[1]=t0.y; a[2]=t0.z; a[3]=t0.w;
                a[4]=t1.x; a[5]=t1.y; a[6]=t1.z; a[7]=t1.w;
                float4 u0 = *(const float4*)&Bs[buf][k*SST + tx*4];
                float4 u1 = *(const float4*)&Bs[buf][k*SST + 64 + tx*4];
                b[0]=u0.x; b[1]=u0.y; b[2]=u0.z; b[3]=u0.w;
                b[4]=u1.x; b[5]=u1.y; b[6]=u1.z; b[7]=u1.w;
            }
            #pragma unroll
            for (int i = 0; i < 8; i++)
                #pragma unroll
                for (int j = 0; j < 8; j++)
                    acc[i][j] += a[i] * b[j];
        }

        As[nb][(c4+0)*SST + row0] = va0.x; As[nb][(c4+1)*SST + row0] = va0.y;
        As[nb][(c4+2)*SST + row0] = va0.z; As[nb][(c4+3)*SST + row0] = va0.w;
        As[nb][(c4+0)*SST + row0+64] = va1.x; As[nb][(c4+1)*SST + row0+64] = va1.y;
        As[nb][(c4+2)*SST + row0+64] = va1.z; As[nb][(c4+3)*SST + row0+64] = va1.w;
        Bs[nb][(c4+0)*SST + row0] = vb0.x; Bs[nb][(c4+1)*SST + row0] = vb0.y;
        Bs[nb][(c4+2)*SST + row0] = vb0.z; Bs[nb][(c4+3)*SST + row0] = vb0.w;
        Bs[nb][(c4+0)*SST + row0+64] = vb1.x; Bs[nb][(c4+1)*SST + row0+64] = vb1.y;
        Bs[nb][(c4+2)*SST + row0+64] = vb1.z; Bs[nb][(c4+3)*SST + row0+64] = vb1.w;
        __syncthreads();
    }
}

// Micro-tile mapping (quadrant-split):
//   acc row index i: global row = m0 + (i<4 ? ty*4+i : 64 + ty*4 + (i-4))
//   acc col index j: global col = n0 + (j<4 ? tx*4+j : 64 + tx*4 + (j-4))

// ---------------------------------------------------------------------------
// Kernel 1: QKV projection. gridDim.z selects Q/K/V. Scatters into [B,H,T,D].
// ---------------------------------------------------------------------------
__global__ __launch_bounds__(256) void qkv_gemm_kernel(
    const float* __restrict__ x,
    const float* __restrict__ Wq, const float* __restrict__ Wk,
    const float* __restrict__ Wv)
{
    __shared__ float As[2][GBK * SST];
    __shared__ float Bs[2][GBK * SST];
    const float* Bw = (blockIdx.z == 0) ? Wq : (blockIdx.z == 1) ? Wk : Wv;
    float* dst      = (blockIdx.z == 0) ? g_Q : (blockIdx.z == 1) ? g_K : g_V;

    const int m0 = blockIdx.y * 128, n0 = blockIdx.x * 128;
    float acc[8][8];
    #pragma unroll
    for (int i = 0; i < 8; i++)
        #pragma unroll
        for (int j = 0; j < 8; j++) acc[i][j] = 0.f;

    gemm_tile_compute(x, Bw, m0, n0, acc, As, Bs);

    const int tx = threadIdx.x & 15, ty = threadIdx.x >> 4;
    #pragma unroll
    for (int ih = 0; ih < 2; ih++) {
        #pragma unroll
        for (int i = 0; i < 4; i++) {
            const int m = m0 + ih * 64 + ty * 4 + i;
            const int b = m >> 11, t = m & 2047;
            #pragma unroll
            for (int jh = 0; jh < 2; jh++) {
                const int n = n0 + jh * 64 + tx * 4;
                const int h = n >> 6, d = n & 63;
                size_t idx = ((size_t)((b * H_ + h) * T_ + t)) * D_ + d;
                *(float4*)&dst[idx] = make_float4(
                    acc[ih*4+i][jh*4+0], acc[ih*4+i][jh*4+1],
                    acc[ih*4+i][jh*4+2], acc[ih*4+i][jh*4+3]);
            }
        }
    }
}

// ---------------------------------------------------------------------------
// Kernel 2: causal flash attention (byte-identical to R1/R12 — known clean)
// ---------------------------------------------------------------------------
#define KST 68   // padded stride for transposed K (68*4B is 16B aligned)

__global__ __launch_bounds__(256) void flash_kernel()
{
    extern __shared__ float sm[];
    float* Qs  = sm;               // 64*64
    float* KsT = Qs + 64 * 64;     // 64*KST (transposed: [d][kv])
    float* Vs  = KsT + 64 * KST;   // 64*64
    float* Ps  = Vs + 64 * 64;     // 64*64

    const int bh = blockIdx.y;
    const int q0 = ((int)gridDim.x - 1 - (int)blockIdx.x) * 64; // heavy tiles first
    const float* Qg = g_Q + (size_t)bh * T_ * D_;
    const float* Kg = g_K + (size_t)bh * T_ * D_;
    const float* Vg = g_V + (size_t)bh * T_ * D_;

    const int tid = threadIdx.x, tx = tid & 15, ty = tid >> 4;

    // Load Q tile, fold in 1/sqrt(D) = 0.125
    #pragma unroll
    for (int rep = 0; rep < 4; rep++) {
        int f = tid + rep * 256;
        int row = f >> 4, c4 = (f & 15) * 4;
        float4 v = *(const float4*)&Qg[(size_t)(q0 + row) * D_ + c4];
        v.x *= 0.125f; v.y *= 0.125f; v.z *= 0.125f; v.w *= 0.125f;
        *(float4*)&Qs[row * 64 + c4] = v;
    }

    float m_i[4], l_i[4], acc[4][4];
    #pragma unroll
    for (int i = 0; i < 4; i++) {
        m_i[i] = -1e30f; l_i[i] = 0.f;
        #pragma unroll
        for (int j = 0; j < 4; j++) acc[i][j] = 0.f;
    }

    for (int kv0 = 0; kv0 <= q0; kv0 += 64) {
        __syncthreads();  // protect Ps/KsT/Vs from previous iteration
        #pragma unroll
        for (int rep = 0; rep < 4; rep++) {
            int f = tid + rep * 256;
            int row = f >> 4, c4 = (f & 15) * 4;
            float4 k4 = *(const float4*)&Kg[(size_t)(kv0 + row) * D_ + c4];
            KsT[(c4+0)*KST + row] = k4.x;
            KsT[(c4+1)*KST + row] = k4.y;
            KsT[(c4+2)*KST + row] = k4.z;
            KsT[(c4+3)*KST + row] = k4.w;
            *(float4*)&Vs[row * 64 + c4] =
                *(const float4*)&Vg[(size_t)(kv0 + row) * D_ + c4];
        }
        __syncthreads();

        // S = Q @ K^T   (scale already folded into Q)
        float s[4][4];
        #pragma unroll
        for (int i = 0; i < 4; i++)
            #pragma unroll
            for (int j = 0; j < 4; j++) s[i][j] = 0.f;

        #pragma unroll
        for (int d4 = 0; d4 < 64; d4 += 4) {
            float qreg[4][4];
            #pragma unroll
            for (int i = 0; i < 4; i++) {
                float4 t = *(const float4*)&Qs[(ty*4 + i) * 64 + d4];
                qreg[i][0]=t.x; qreg[i][1]=t.y; qreg[i][2]=t.z; qreg[i][3]=t.w;
            }
            #pragma unroll
            for (int dd = 0; dd < 4; dd++) {
                float4 kv = *(const float4*)&KsT[(d4 + dd) * KST + tx * 4];
                #pragma unroll
                for (int i = 0; i < 4; i++) {
                    s[i][0] += qreg[i][dd] * kv.x;
                    s[i][1] += qreg[i][dd] * kv.y;
                    s[i][2] += qreg[i][dd] * kv.z;
                    s[i][3] += qreg[i][dd] * kv.w;
                }
            }
        }

        if (kv0 == q0) {   // diagonal tile: causal mask (local col > local row)
            #pragma unroll
            for (int i = 0; i < 4; i++)
                #pragma unroll
                for (int j = 0; j < 4; j++)
                    if (tx * 4 + j > ty * 4 + i) s[i][j] = -1e30f;
        }

        // Online softmax update per row
        #pragma unroll
        for (int i = 0; i < 4; i++) {
            float mloc = fmaxf(fmaxf(s[i][0], s[i][1]), fmaxf(s[i][2], s[i][3]));
            #pragma unroll
            for (int off = 8; off > 0; off >>= 1)
                mloc = fmaxf(mloc, __shfl_xor_sync(0xffffffffu, mloc, off));
            float mnew = fmaxf(m_i[i], mloc);
            float corr = __expf(m_i[i] - mnew);
            m_i[i] = mnew;
            float rs = 0.f;
            #pragma unroll
            for (int j = 0; j < 4; j++) {
                float p = __expf(s[i][j] - mnew);
                s[i][j] = p; rs += p;
            }
            #pragma unroll
            for (int off = 8; off > 0; off >>= 1)
                rs += __shfl_xor_sync(0xffffffffu, rs, off);
            l_i[i] = l_i[i] * corr + rs;
            #pragma unroll
            for (int j = 0; j < 4; j++) acc[i][j] *= corr;
            *(float4*)&Ps[(ty*4 + i) * 64 + tx * 4] =
                make_float4(s[i][0], s[i][1], s[i][2], s[i][3]);
        }
        __syncthreads();

        // O += P @ V
        #pragma unroll
        for (int kv4 = 0; kv4 < 64; kv4 += 4) {
            float preg[4][4];
            #pragma unroll
            for (int i = 0; i < 4; i++) {
                float4 t = *(const float4*)&Ps[(ty*4 + i) * 64 + kv4];
                preg[i][0]=t.x; preg[i][1]=t.y; preg[i][2]=t.z; preg[i][3]=t.w;
            }
            #pragma unroll
            for (int kk = 0; kk < 4; kk++) {
                float4 v = *(const float4*)&Vs[(kv4 + kk) * 64 + tx * 4];
                #pragma unroll
                for (int i = 0; i < 4; i++) {
                    acc[i][0] += preg[i][kk] * v.x;
                    acc[i][1] += preg[i][kk] * v.y;
                    acc[i][2] += preg[i][kk] * v.z;
                    acc[i][3] += preg[i][kk] * v.w;
                }
            }
        }
    }

    // Normalize and write to [B,T,C] layout for the output projection
    const int b = bh >> 4, h = bh & 15;
    #pragma unroll
    for (int i = 0; i < 4; i++) {
        int q = q0 + ty * 4 + i;
        float inv = 1.0f / l_i[i];
        float4 o = make_float4(acc[i][0]*inv, acc[i][1]*inv, acc[i][2]*inv, acc[i][3]*inv);
        *(float4*)&g_A[((size_t)(b * T_ + q)) * C_ + h * D_ + tx * 4] = o;
    }
}

// ---------------------------------------------------------------------------
// Kernel 3: output projection + bias
// ---------------------------------------------------------------------------
__global__ __launch_bounds__(256) void outproj_kernel(
    const float* __restrict__ Wo, const float* __restrict__ bo,
    float* __restrict__ out)
{
    __shared__ float As[2][GBK * SST];
    __shared__ float Bs[2][GBK * SST];
    const int m0 = blockIdx.y * 128, n0 = blockIdx.x * 128;
    float acc[8][8];
    #pragma unroll
    for (int i = 0; i < 8; i++)
        #pragma unroll
        for (int j = 0; j < 8; j++) acc[i][j] = 0.f;

    gemm_tile_compute(g_A, Wo, m0, n0, acc, As, Bs);

    const int tx = threadIdx.x & 15, ty = threadIdx.x >> 4;
    #pragma unroll
    for (int ih = 0; ih < 2; ih++) {
        #pragma unroll
        for (int i = 0; i < 4; i++) {
            const int m = m0 + ih * 64 + ty * 4 + i;
            #pragma unroll
            for (int jh = 0; jh < 2; jh++) {
                const int n = n0 + jh * 64 + tx * 4;
                float4 bias = *(const float4*)&bo[n];
                *(float4*)&out[(size_t)m * C_ + n] = make_float4(
                    acc[ih*4+i][jh*4+0] + bias.x, acc[ih*4+i][jh*4+1] + bias.y,
                    acc[ih*4+i][jh*4+2] + bias.z, acc[ih*4+i][jh*4+3] + bias.w);
            }
        }
    }
}

// ---------------------------------------------------------------------------
extern "C" void kernel_launch(void* const* d_in, const int* in_sizes, int n_in,
                              void* d_out, int out_size)
{
    const float* x  = (const float*)d_in[0];
    const float* Wq = (const float*)d_in[1];
    const float* Wk = (const float*)d_in[2];
    const float* Wv = (const float*)d_in[3];
    const float* Wo = (const float*)d_in[4];
    const float* bo = (const float*)d_in[5];
    float* out = (float*)d_out;

    const int FLASH_SMEM = (64*64 + 64*KST + 64*64 + 64*64) * 4;  // 66560 B
    cudaFuncSetAttribute(flash_kernel,
                         cudaFuncAttributeMaxDynamicSharedMemorySize, FLASH_SMEM);

    dim3 gq(C_ / 128, M_ / 128, 3);     // (8, 32, 3)
    qkv_gemm_kernel<<<gq, 256>>>(x, Wq, Wk, Wv);

    flash_kernel<<<dim3(T_ / 64, B_ * H_), 256, FLASH_SMEM>>>();

    dim3 go(C_ / 128, M_ / 128, 1);     // (8, 32)
    outproj_kernel<<<go, 256>>>(Wo, bo, out);
}

// round 15
// speedup vs baseline: 1.0753x; 1.0216x over previous
#include <cuda_runtime.h>
#include <cstdint>

#define B_ 2
#define T_ 2048
#define C_ 1024
#define H_ 16
#define D_ 64
#define M_ (B_*T_)   // 4096 rows

// Scratch (no allocations allowed — device globals)
__device__ float g_Q[B_*H_*T_*D_];
__device__ float g_K[B_*H_*T_*D_];
__device__ float g_V[B_*H_*T_*D_];
__device__ float g_A[M_*C_];

// ---------------------------------------------------------------------------
// Generic 128x128 fp32 GEMM tile (byte-identical to R14 — measured good)
// ---------------------------------------------------------------------------
#define GBK 16
#define SST 132
#define NKB (C_/GBK)   // 64

__device__ __forceinline__ void gemm_tile_compute(
    const float* __restrict__ A, const float* __restrict__ Bw,
    int m0, int n0, float acc[8][8],
    float (*As)[GBK * SST], float (*Bs)[GBK * SST])
{
    const int tid = threadIdx.x;
    const int tx = tid & 15, ty = tid >> 4;
    const int row0 = tid >> 2;          // 0..63
    const int c4   = (tid & 3) * 4;     // 0,4,8,12
    const float* Ap0 = &A[(size_t)(m0 + row0)      * C_ + c4];
    const float* Ap1 = &A[(size_t)(m0 + row0 + 64) * C_ + c4];
    const float* Bp0 = &Bw[(size_t)(n0 + row0)      * C_ + c4];
    const float* Bp1 = &Bw[(size_t)(n0 + row0 + 64) * C_ + c4];

    float4 va0 = *(const float4*)(Ap0);
    float4 va1 = *(const float4*)(Ap1);
    float4 vb0 = *(const float4*)(Bp0);
    float4 vb1 = *(const float4*)(Bp1);
    As[0][(c4+0)*SST + row0] = va0.x; As[0][(c4+1)*SST + row0] = va0.y;
    As[0][(c4+2)*SST + row0] = va0.z; As[0][(c4+3)*SST + row0] = va0.w;
    As[0][(c4+0)*SST + row0+64] = va1.x; As[0][(c4+1)*SST + row0+64] = va1.y;
    As[0][(c4+2)*SST + row0+64] = va1.z; As[0][(c4+3)*SST + row0+64] = va1.w;
    Bs[0][(c4+0)*SST + row0] = vb0.x; Bs[0][(c4+1)*SST + row0] = vb0.y;
    Bs[0][(c4+2)*SST + row0] = vb0.z; Bs[0][(c4+3)*SST + row0] = vb0.w;
    Bs[0][(c4+0)*SST + row0+64] = vb1.x; Bs[0][(c4+1)*SST + row0+64] = vb1.y;
    Bs[0][(c4+2)*SST + row0+64] = vb1.z; Bs[0][(c4+3)*SST + row0+64] = vb1.w;
    __syncthreads();

    for (int kb = 0; kb < NKB; kb++) {
        const int buf = kb & 1;
        const int nb  = buf ^ 1;
        const int kn = (kb + 1 < NKB) ? (kb + 1) * GBK : kb * GBK;
        va0 = *(const float4*)(Ap0 + kn);
        va1 = *(const float4*)(Ap1 + kn);
        vb0 = *(const float4*)(Bp0 + kn);
        vb1 = *(const float4*)(Bp1 + kn);

        #pragma unroll
        for (int k = 0; k < GBK; k++) {
            float a[8], b[8];
            {
                float4 t0 = *(const float4*)&As[buf][k*SST + ty*4];
                float4 t1 = *(const float4*)&As[buf][k*SST + 64 + ty*4];
                a[0]=t0.x; a[1]=t0.y; a[2]=t0.z; a[3]=t0.w;
                a[4]=t1.x; a[5]=t1.y; a[6]=t1.z; a[7]=t1.w;
                float4 u0 = *(const float4*)&Bs[buf][k*SST + tx*4];
                float4 u1 = *(const float4*)&Bs[buf][k*SST + 64 + tx*4];
                b[0]=u0.x; b[1]=u0.y; b[2]=u0.z; b[3]=u0.w;
                b[4]=u1.x; b[5]=u1.y; b[6]=u1.z; b[7]=u1.w;
            }
            #pragma unroll
            for (int i = 0; i < 8; i++)
                #pragma unroll
                for (int j = 0; j < 8; j++)
                    acc[i][j] += a[i] * b[j];
        }

        As[nb][(c4+0)*SST + row0] = va0.x; As[nb][(c4+1)*SST + row0] = va0.y;
        As[nb][(c4+2)*SST + row0] = va0.z; As[nb][(c4+3)*SST + row0] = va0.w;
        As[nb][(c4+0)*SST + row0+64] = va1.x; As[nb][(c4+1)*SST + row0+64] = va1.y;
        As[nb][(c4+2)*SST + row0+64] = va1.z; As[nb][(c4+3)*SST + row0+64] = va1.w;
        Bs[nb][(c4+0)*SST + row0] = vb0.x; Bs[nb][(c4+1)*SST + row0] = vb0.y;
        Bs[nb][(c4+2)*SST + row0] = vb0.z; Bs[nb][(c4+3)*SST + row0] = vb0.w;
        Bs[nb][(c4+0)*SST + row0+64] = vb1.x; Bs[nb][(c4+1)*SST + row0+64] = vb1.y;
        Bs[nb][(c4+2)*SST + row0+64] = vb1.z; Bs[nb][(c4+3)*SST + row0+64] = vb1.w;
        __syncthreads();
    }
}

// ---------------------------------------------------------------------------
// Kernel 1: QKV projection (byte-identical to R14)
// ---------------------------------------------------------------------------
__global__ __launch_bounds__(256) void qkv_gemm_kernel(
    const float* __restrict__ x,
    const float* __restrict__ Wq, const float* __restrict__ Wk,
    const float* __restrict__ Wv)
{
    __shared__ float As[2][GBK * SST];
    __shared__ float Bs[2][GBK * SST];
    const float* Bw = (blockIdx.z == 0) ? Wq : (blockIdx.z == 1) ? Wk : Wv;
    float* dst      = (blockIdx.z == 0) ? g_Q : (blockIdx.z == 1) ? g_K : g_V;

    const int m0 = blockIdx.y * 128, n0 = blockIdx.x * 128;
    float acc[8][8];
    #pragma unroll
    for (int i = 0; i < 8; i++)
        #pragma unroll
        for (int j = 0; j < 8; j++) acc[i][j] = 0.f;

    gemm_tile_compute(x, Bw, m0, n0, acc, As, Bs);

    const int tx = threadIdx.x & 15, ty = threadIdx.x >> 4;
    #pragma unroll
    for (int ih = 0; ih < 2; ih++) {
        #pragma unroll
        for (int i = 0; i < 4; i++) {
            const int m = m0 + ih * 64 + ty * 4 + i;
            const int b = m >> 11, t = m & 2047;
            #pragma unroll
            for (int jh = 0; jh < 2; jh++) {
                const int n = n0 + jh * 64 + tx * 4;
                const int h = n >> 6, d = n & 63;
                size_t idx = ((size_t)((b * H_ + h) * T_ + t)) * D_ + d;
                *(float4*)&dst[idx] = make_float4(
                    acc[ih*4+i][jh*4+0], acc[ih*4+i][jh*4+1],
                    acc[ih*4+i][jh*4+2], acc[ih*4+i][jh*4+3]);
            }
        }
    }
}

// ---------------------------------------------------------------------------
// Kernel 2: causal flash attention v2
//  - unconditional register prefetch of next K/V tile (LDG hidden by compute)
//  - K loader remapped (lanes span consecutive rows) -> conflict-free KsT STS
// ---------------------------------------------------------------------------
#define KST 68

__global__ __launch_bounds__(256) void flash_kernel()
{
    extern __shared__ float sm[];
    float* Qs  = sm;               // 64*64
    float* KsT = Qs + 64 * 64;     // [d][kv], stride KST
    float* Vs  = KsT + 64 * KST;   // 64*64
    float* Ps  = Vs + 64 * 64;     // 64*64

    const int bh = blockIdx.y;
    const int q0 = ((int)gridDim.x - 1 - (int)blockIdx.x) * 64; // heavy tiles first
    const float* Qg = g_Q + (size_t)bh * T_ * D_;
    const float* Kg = g_K + (size_t)bh * T_ * D_;
    const float* Vg = g_V + (size_t)bh * T_ * D_;

    const int tid = threadIdx.x, tx = tid & 15, ty = tid >> 4;

    // K loader mapping: lanes cover consecutive rows, column fixed per warp.
    const int rowK = tid & 63;              // consecutive within a warp
    const int cKb  = (tid >> 6) * 4;        // + rep*16 per rep
    // V loader mapping (row-major, unchanged style)
    const int rowVb = tid >> 4;             // + rep*16 per rep
    const int cV    = (tid & 15) * 4;

    // Load Q tile, fold in 1/sqrt(D) = 0.125
    #pragma unroll
    for (int rep = 0; rep < 4; rep++) {
        int f = tid + rep * 256;
        int row = f >> 4, c4 = (f & 15) * 4;
        float4 v = *(const float4*)&Qg[(size_t)(q0 + row) * D_ + c4];
        v.x *= 0.125f; v.y *= 0.125f; v.z *= 0.125f; v.w *= 0.125f;
        *(float4*)&Qs[row * 64 + c4] = v;
    }

    // Prologue: load K/V tile 0 into SMEM
    {
        float4 k0 = *(const float4*)&Kg[(size_t)rowK * D_ + cKb];
        float4 k1 = *(const float4*)&Kg[(size_t)rowK * D_ + cKb + 16];
        float4 k2 = *(const float4*)&Kg[(size_t)rowK * D_ + cKb + 32];
        float4 k3 = *(const float4*)&Kg[(size_t)rowK * D_ + cKb + 48];
        float4 v0 = *(const float4*)&Vg[(size_t)(rowVb)      * D_ + cV];
        float4 v1 = *(const float4*)&Vg[(size_t)(rowVb + 16) * D_ + cV];
        float4 v2 = *(const float4*)&Vg[(size_t)(rowVb + 32) * D_ + cV];
        float4 v3 = *(const float4*)&Vg[(size_t)(rowVb + 48) * D_ + cV];
        KsT[(cKb+0)*KST + rowK] = k0.x; KsT[(cKb+1)*KST + rowK] = k0.y;
        KsT[(cKb+2)*KST + rowK] = k0.z; KsT[(cKb+3)*KST + rowK] = k0.w;
        KsT[(cKb+16)*KST + rowK] = k1.x; KsT[(cKb+17)*KST + rowK] = k1.y;
        KsT[(cKb+18)*KST + rowK] = k1.z; KsT[(cKb+19)*KST + rowK] = k1.w;
        KsT[(cKb+32)*KST + rowK] = k2.x; KsT[(cKb+33)*KST + rowK] = k2.y;
        KsT[(cKb+34)*KST + rowK] = k2.z; KsT[(cKb+35)*KST + rowK] = k2.w;
        KsT[(cKb+48)*KST + rowK] = k3.x; KsT[(cKb+49)*KST + rowK] = k3.y;
        KsT[(cKb+50)*KST + rowK] = k3.z; KsT[(cKb+51)*KST + rowK] = k3.w;
        *(float4*)&Vs[(rowVb)      * 64 + cV] = v0;
        *(float4*)&Vs[(rowVb + 16) * 64 + cV] = v1;
        *(float4*)&Vs[(rowVb + 32) * 64 + cV] = v2;
        *(float4*)&Vs[(rowVb + 48) * 64 + cV] = v3;
    }
    __syncthreads();

    float m_i[4], l_i[4], acc[4][4];
    #pragma unroll
    for (int i = 0; i < 4; i++) {
        m_i[i] = -1e30f; l_i[i] = 0.f;
        #pragma unroll
        for (int j = 0; j < 4; j++) acc[i][j] = 0.f;
    }

    for (int kv0 = 0; kv0 <= q0; kv0 += 64) {
        // Unconditional prefetch of NEXT tile (clamped on last iteration:
        // in-bounds re-read, stores redundant identical data — harmless).
        const int kvn = (kv0 + 64 <= q0) ? (kv0 + 64) : kv0;
        float4 pk0 = *(const float4*)&Kg[(size_t)(kvn + rowK) * D_ + cKb];
        float4 pk1 = *(const float4*)&Kg[(size_t)(kvn + rowK) * D_ + cKb + 16];
        float4 pk2 = *(const float4*)&Kg[(size_t)(kvn + rowK) * D_ + cKb + 32];
        float4 pk3 = *(const float4*)&Kg[(size_t)(kvn + rowK) * D_ + cKb + 48];
        float4 pv0 = *(const float4*)&Vg[(size_t)(kvn + rowVb)      * D_ + cV];
        float4 pv1 = *(const float4*)&Vg[(size_t)(kvn + rowVb + 16) * D_ + cV];
        float4 pv2 = *(const float4*)&Vg[(size_t)(kvn + rowVb + 32) * D_ + cV];
        float4 pv3 = *(const float4*)&Vg[(size_t)(kvn + rowVb + 48) * D_ + cV];

        // S = Q @ K^T   (scale folded into Q)
        float s[4][4];
        #pragma unroll
        for (int i = 0; i < 4; i++)
            #pragma unroll
            for (int j = 0; j < 4; j++) s[i][j] = 0.f;

        #pragma unroll
        for (int d4 = 0; d4 < 64; d4 += 4) {
            float qreg[4][4];
            #pragma unroll
            for (int i = 0; i < 4; i++) {
                float4 t = *(const float4*)&Qs[(ty*4 + i) * 64 + d4];
                qreg[i][0]=t.x; qreg[i][1]=t.y; qreg[i][2]=t.z; qreg[i][3]=t.w;
            }
            #pragma unroll
            for (int dd = 0; dd < 4; dd++) {
                float4 kv = *(const float4*)&KsT[(d4 + dd) * KST + tx * 4];
                #pragma unroll
                for (int i = 0; i < 4; i++) {
                    s[i][0] += qreg[i][dd] * kv.x;
                    s[i][1] += qreg[i][dd] * kv.y;
                    s[i][2] += qreg[i][dd] * kv.z;
                    s[i][3] += qreg[i][dd] * kv.w;
                }
            }
        }

        if (kv0 == q0) {   // diagonal tile: causal mask
            #pragma unroll
            for (int i = 0; i < 4; i++)
                #pragma unroll
                for (int j = 0; j < 4; j++)
                    if (tx * 4 + j > ty * 4 + i) s[i][j] = -1e30f;
        }

        // Online softmax update per row
        #pragma unroll
        for (int i = 0; i < 4; i++) {
            float mloc = fmaxf(fmaxf(s[i][0], s[i][1]), fmaxf(s[i][2], s[i][3]));
            #pragma unroll
            for (int off = 8; off > 0; off >>= 1)
                mloc = fmaxf(mloc, __shfl_xor_sync(0xffffffffu, mloc, off));
            float mnew = fmaxf(m_i[i], mloc);
            float corr = __expf(m_i[i] - mnew);
            m_i[i] = mnew;
            float rs = 0.f;
            #pragma unroll
            for (int j = 0; j < 4; j++) {
                float p = __expf(s[i][j] - mnew);
                s[i][j] = p; rs += p;
            }
            #pragma unroll
            for (int off = 8; off > 0; off >>= 1)
                rs += __shfl_xor_sync(0xffffffffu, rs, off);
            l_i[i] = l_i[i] * corr + rs;
            #pragma unroll
            for (int j = 0; j < 4; j++) acc[i][j] *= corr;
            *(float4*)&Ps[(ty*4 + i) * 64 + tx * 4] =
                make_float4(s[i][0], s[i][1], s[i][2], s[i][3]);
        }
        __syncthreads();   // Ps visible

        // O += P @ V
        #pragma unroll
        for (int kv4 = 0; kv4 < 64; kv4 += 4) {
            float preg[4][4];
            #pragma unroll
            for (int i = 0; i < 4; i++) {
                float4 t = *(const float4*)&Ps[(ty*4 + i) * 64 + kv4];
                preg[i][0]=t.x; preg[i][1]=t.y; preg[i][2]=t.z; preg[i][3]=t.w;
            }
            #pragma unroll
            for (int kk = 0; kk < 4; kk++) {
                float4 v = *(const float4*)&Vs[(kv4 + kk) * 64 + tx * 4];
                #pragma unroll
                for (int i = 0; i < 4; i++) {
                    acc[i][0] += preg[i][kk] * v.x;
                    acc[i][1] += preg[i][kk] * v.y;
                    acc[i][2] += preg[i][kk] * v.z;
                    acc[i][3] += preg[i][kk] * v.w;
                }
            }
        }
        __syncthreads();   // everyone done reading KsT/Vs of this tile

        // Store prefetched next tile (conflict-free K stores)
        KsT[(cKb+0)*KST + rowK] = pk0.x; KsT[(cKb+1)*KST + rowK] = pk0.y;
        KsT[(cKb+2)*KST + rowK] = pk0.z; KsT[(cKb+3)*KST + rowK] = pk0.w;
        KsT[(cKb+16)*KST + rowK] = pk1.x; KsT[(cKb+17)*KST + rowK] = pk1.y;
        KsT[(cKb+18)*KST + rowK] = pk1.z; KsT[(cKb+19)*KST + rowK] = pk1.w;
        KsT[(cKb+32)*KST + rowK] = pk2.x; KsT[(cKb+33)*KST + rowK] = pk2.y;
        KsT[(cKb+34)*KST + rowK] = pk2.z; KsT[(cKb+35)*KST + rowK] = pk2.w;
        KsT[(cKb+48)*KST + rowK] = pk3.x; KsT[(cKb+49)*KST + rowK] = pk3.y;
        KsT[(cKb+50)*KST + rowK] = pk3.z; KsT[(cKb+51)*KST + rowK] = pk3.w;
        *(float4*)&Vs[(rowVb)      * 64 + cV] = pv0;
        *(float4*)&Vs[(rowVb + 16) * 64 + cV] = pv1;
        *(float4*)&Vs[(rowVb + 32) * 64 + cV] = pv2;
        *(float4*)&Vs[(rowVb + 48) * 64 + cV] = pv3;
        __syncthreads();   // stores visible for next iteration
    }

    // Normalize and write to [B,T,C] layout for the output projection
    const int b = bh >> 4, h = bh & 15;
    #pragma unroll
    for (int i = 0; i < 4; i++) {
        int q = q0 + ty * 4 + i;
        float inv = 1.0f / l_i[i];
        float4 o = make_float4(acc[i][0]*inv, acc[i][1]*inv, acc[i][2]*inv, acc[i][3]*inv);
        *(float4*)&g_A[((size_t)(b * T_ + q)) * C_ + h * D_ + tx * 4] = o;
    }
}

// ---------------------------------------------------------------------------
// Kernel 3: output projection + bias (byte-identical to R14)
// ---------------------------------------------------------------------------
__global__ __launch_bounds__(256) void outproj_kernel(
    const float* __restrict__ Wo, const float* __restrict__ bo,
    float* __restrict__ out)
{
    __shared__ float As[2][GBK * SST];
    __shared__ float Bs[2][GBK * SST];
    const int m0 = blockIdx.y * 128, n0 = blockIdx.x * 128;
    float acc[8][8];
    #pragma unroll
    for (int i = 0; i < 8; i++)
        #pragma unroll
        for (int j = 0; j < 8; j++) acc[i][j] = 0.f;

    gemm_tile_compute(g_A, Wo, m0, n0, acc, As, Bs);

    const int tx = threadIdx.x & 15, ty = threadIdx.x >> 4;
    #pragma unroll
    for (int ih = 0; ih < 2; ih++) {
        #pragma unroll
        for (int i = 0; i < 4; i++) {
            const int m = m0 + ih * 64 + ty * 4 + i;
            #pragma unroll
            for (int jh = 0; jh < 2; jh++) {
                const int n = n0 + jh * 64 + tx * 4;
                float4 bias = *(const float4*)&bo[n];
                *(float4*)&out[(size_t)m * C_ + n] = make_float4(
                    acc[ih*4+i][jh*4+0] + bias.x, acc[ih*4+i][jh*4+1] + bias.y,
                    acc[ih*4+i][jh*4+2] + bias.z, acc[ih*4+i][jh*4+3] + bias.w);
            }
        }
    }
}

// ---------------------------------------------------------------------------
extern "C" void kernel_launch(void* const* d_in, const int* in_sizes, int n_in,
                              void* d_out, int out_size)
{
    const float* x  = (const float*)d_in[0];
    const float* Wq = (const float*)d_in[1];
    const float* Wk = (const float*)d_in[2];
    const float* Wv = (const float*)d_in[3];
    const float* Wo = (const float*)d_in[4];
    const float* bo = (const float*)d_in[5];
    float* out = (float*)d_out;

    const int FLASH_SMEM = (64*64 + 64*KST + 64*64 + 64*64) * 4;  // 66560 B
    cudaFuncSetAttribute(flash_kernel,
                         cudaFuncAttributeMaxDynamicSharedMemorySize, FLASH_SMEM);

    dim3 gq(C_ / 128, M_ / 128, 3);     // (8, 32, 3)
    qkv_gemm_kernel<<<gq, 256>>>(x, Wq, Wk, Wv);

    flash_kernel<<<dim3(T_ / 64, B_ * H_), 256, FLASH_SMEM>>>();

    dim3 go(C_ / 128, M_ / 128, 1);     // (8, 32)
    outproj_kernel<<<go, 256>>>(Wo, bo, out);
}